// round 7
// baseline (speedup 1.0000x reference)
#include <cuda_runtime.h>
#include <math.h>

// ---------------------------------------------------------------------------
// GP marginal log-likelihood, T=8192, RBF(l=32) + sigma^2 I.  ONE persistent
// kernel, 128 CTAs x 128 threads, all co-resident:
//   logdet : strong Szego  logdet = T*c0 + sum k*c_k^2  (c_k of log-symbol)
//   quad   : FULLY LOCAL windowed CG per CTA.  A^{-1} decays e^{-0.031|i-j|}
//            (analyticity strip of 1/f), so each CTA solves its clamped
//            512-point principal-submatrix system (64-chunk + 224 halo,
//            zero-Dirichlet masks) independently: ZERO cross-CTA sync in the
//            iteration.  Band 128 matvec in smem.
// Only 2 grid barriers total (symbol->Szego, partials->combine).
// Deterministic: fixed-order reductions, no fp atomics.
// ---------------------------------------------------------------------------

#define T_N   8192
#define NCTA  128
#define NTHR  128
#define CHUNK 64
#define HW    224               // window half-pad (truncation err ~e^{-0.031*224})
#define WV    (CHUNK + 2*HW)    // 512 window slots
#define BCV   128               // matvec half-band
#define PADW  (BCV + WV + BCV)  // 768 padded smem vector
#define BTAPS 256               // symbol taps
#define NGRID 16384
#define NHALF 8192
#define NIT   34                // CG iterations

__device__ float    g_logf[NHALF + 1];
__device__ double   g_szpart[NCTA];
__device__ double   g_qpart[NCTA];
__device__ double   g_c0;
__device__ unsigned g_cnt;
__device__ volatile unsigned g_gen;

__device__ __forceinline__ double warp_redd(double v) {
    #pragma unroll
    for (int o = 16; o; o >>= 1) v += __shfl_down_sync(0xffffffffu, v, o);
    return v;
}
__device__ __forceinline__ float warp_redf(float v) {
    #pragma unroll
    for (int o = 16; o; o >>= 1) v += __shfl_down_sync(0xffffffffu, v, o);
    return v;
}

// Grid-wide barrier (all NCTA CTAs resident).
__device__ __forceinline__ void gbar() {
    __syncthreads();
    if (threadIdx.x == 0) {
        __threadfence();
        unsigned gen = g_gen;
        if (atomicAdd(&g_cnt, 1u) == NCTA - 1u) {
            g_cnt = 0u;
            __threadfence();
            g_gen = gen + 1u;
        } else {
            while (g_gen == gen) { __nanosleep(64); }
        }
        __threadfence();
    }
    __syncthreads();
}

__global__ void __launch_bounds__(NTHR, 1)
gp_fused(const float* __restrict__ y,   const float* __restrict__ ssq,
         const float* __restrict__ ls,  const float* __restrict__ var,
         float* __restrict__ out)
{
    __shared__ float  s_tap[BTAPS + 1];
    __shared__ float  s_p[PADW];
    __shared__ double s_red[4];
    __shared__ double s_sz[4];
    __shared__ double s_ck2[2];

    const int t    = threadIdx.x;
    const int cta  = blockIdx.x;
    const int warp = t >> 5;
    const int lane = t & 31;

    // block-wide reduction, result broadcast to all threads (fixed order)
    auto block_red = [&](double v) -> double {
        v = warp_redd(v);
        if (lane == 0) s_red[warp] = v;
        __syncthreads();
        double s = s_red[0] + s_red[1] + s_red[2] + s_red[3];
        __syncthreads();
        return s;
    };

    // ---------------- taps (every CTA, redundant — cheaper than a sync) -----
    {
        double L = (double)ls[0], V = (double)var[0], s2 = (double)ssq[0];
        double inv2 = 1.0 / (2.0 * L * L);
        for (int d = t; d <= BTAPS; d += NTHR) {
            double v = V * exp(-(double)d * (double)d * inv2);
            if (d == 0) v += s2;
            s_tap[d] = (float)v;
        }
    }
    for (int i = t; i < PADW; i += NTHR) s_p[i] = 0.f;
    __syncthreads();

    // ---------------- fully local windowed CG --------------------------------
    const int base = cta * CHUNK - HW;          // global index of window slot 0
    float x4[4], r4[4], p4[4], y4[4], mk[4];
    double acc0 = 0.0;
    #pragma unroll
    for (int q = 0; q < 4; q++) {
        int i = t + 128 * q;
        int g = base + i;
        bool val = (g >= 0 && g < T_N);
        float yv = val ? y[g] : 0.f;
        mk[q] = val ? 1.f : 0.f;
        y4[q] = yv; x4[q] = 0.f; r4[q] = yv; p4[q] = yv;
        s_p[BCV + i] = yv;
        acc0 += (double)yv * (double)yv;
    }
    double rho = block_red(acc0);               // also publishes s_p

    for (int it = 0; it < NIT; it++) {
        // matvec Ap on window (zero-Dirichlet via pads/masks) + p.Ap
        float ap4[4];
        double pap = 0.0;
        #pragma unroll
        for (int q = 0; q < 4; q++) {
            int c = BCV + t + 128 * q;
            float a = s_tap[0] * s_p[c];
            #pragma unroll 8
            for (int d = 1; d <= BCV; d++)
                a += s_tap[d] * (s_p[c - d] + s_p[c + d]);
            ap4[q] = a;
            pap += (double)p4[q] * (double)a;   // p=0 at invalid slots
        }
        double paps = block_red(pap);
        float alpha = (float)(rho / paps);

        double rr = 0.0;
        #pragma unroll
        for (int q = 0; q < 4; q++) {
            x4[q] += alpha * p4[q];
            float rv = (r4[q] - alpha * ap4[q]) * mk[q];
            r4[q] = rv;
            rr += (double)rv * (double)rv;
        }
        double rhon = block_red(rr);
        float beta = (float)(rhon / rho);
        rho = rhon;

        #pragma unroll
        for (int q = 0; q < 4; q++) {
            float pv = r4[q] + beta * p4[q];
            p4[q] = pv;
            s_p[BCV + t + 128 * q] = pv;
        }
        __syncthreads();
    }

    // quad partial over OWN interior chunk: window slots [HW, HW+CHUNK)
    {
        double qd = 0.0;
        #pragma unroll
        for (int q = 0; q < 4; q++) {
            int i = t + 128 * q;
            if (i >= HW && i < HW + CHUNK)
                qd += (double)y4[q] * (double)x4[q];
        }
        qd = block_red(qd);
        if (t == 0) g_qpart[cta] = qd;
    }

    // ---------------- symbol: logf[j], 64 j's per CTA ------------------------
    {
        int j = -1;
        if (t < 64) j = cta * 64 + t;
        else if (cta == NCTA - 1 && t == 64) j = NHALF;
        if (j >= 0) {
            const float sc = 1.0f / 8192.0f;
            float acc = 0.f;
            for (int d = 1; d < BTAPS; d++) {
                int m = (j * d) & (NGRID - 1);
                acc += s_tap[d] * cospif((float)m * sc);
            }
            g_logf[j] = logf(s_tap[0] + 2.f * acc);
        }
    }
    gbar();

    // ---------------- Szego partials: 2 harmonics per CTA (2 warps each) -----
    {
        int k    = cta * 2 + (warp >> 1);       // 0..255
        int half = warp & 1;
        const float sc = 1.0f / 8192.0f;
        float part = 0.f;
        for (int j = 1 + lane + 32 * half; j < NHALF; j += 64) {
            int m = (j * k) & (NGRID - 1);
            part += g_logf[j] * cospif((float)m * sc);
        }
        part = warp_redf(part);
        if (lane == 0) s_sz[warp] = (double)part;
        __syncthreads();
        if (t == 0 || t == 64) {
            int w2 = t >> 5;                     // 0 or 2
            int kk = cta * 2 + (w2 >> 1);
            double s = (double)g_logf[0]
                     + ((kk & 1) ? -(double)g_logf[NHALF] : (double)g_logf[NHALF])
                     + 2.0 * (s_sz[w2] + s_sz[w2 + 1]);
            double ck = s / (double)NGRID;
            if (kk == 0) { g_c0 = ck; s_ck2[0] = 0.0; }
            else         s_ck2[w2 >> 1] = (double)kk * ck * ck;
        }
        __syncthreads();
        if (t == 0) g_szpart[cta] = s_ck2[0] + s_ck2[1];
    }
    gbar();

    // ---------------- combine (CTA 0) ----------------------------------------
    if (cta == 0) {
        double q  = __ldcg(&g_qpart[t]);        // bypass L1 (own stale lines)
        double sz = __ldcg(&g_szpart[t]);
        q  = warp_redd(q);
        sz = warp_redd(sz);
        if (lane == 0) { s_red[warp] = q; s_sz[warp] = sz; }
        __syncthreads();
        if (t == 0) {
            double Q  = s_red[0] + s_red[1] + s_red[2] + s_red[3];
            double SZ = s_sz[0]  + s_sz[1]  + s_sz[2]  + s_sz[3];
            double logdet = (double)T_N * g_c0 + SZ;
            out[0] = (float)(-0.5 * Q - 0.5 * logdet);
        }
    }
}

extern "C" void kernel_launch(void* const* d_in, const int* in_sizes, int n_in,
                              void* d_out, int out_size) {
    const float* y   = (const float*)d_in[0];
    const float* ssq = (const float*)d_in[1];
    const float* ls  = (const float*)d_in[2];
    const float* var = (const float*)d_in[3];
    float* out = (float*)d_out;
    gp_fused<<<NCTA, NTHR>>>(y, ssq, ls, var, out);
}

// round 13
// speedup vs baseline: 1.4962x; 1.4962x over previous
#include <cuda_runtime.h>
#include <math.h>

// ---------------------------------------------------------------------------
// GP marginal log-likelihood, T=8192, RBF(l=32) + sigma^2 I.  ONE persistent
// kernel, 128 CTAs x 256 threads, all co-resident:
//   logdet : strong Szego  logdet = T*c0 + sum k*c_k^2  (c_k of log-symbol)
//   quad   : FULLY LOCAL windowed CG per CTA (A^{-1} decay e^{-0.031|i-j|}):
//            clamped 448-point principal-submatrix window (64-chunk + 192
//            halo), zero cross-CTA sync in the iteration.  Band-128 matvec.
// R8 vs R7: 256 thr/CTA (2 warps/SMSP for latency hiding), 4 accumulators
// per output (break FADD chain), NIT 34->24, window 512->448.
// R9: clamp dead-slot matvec index (removes masked OOB shared read).
// ---------------------------------------------------------------------------

#define T_N   8192
#define NCTA  128
#define NTHR  256
#define CHUNK 64
#define HW    192               // window half-pad
#define WV    (CHUNK + 2*HW)    // 448 window slots
#define BCV   128               // matvec half-band
#define PADW  (BCV + WV + BCV)  // 704 padded smem vector
#define BTAPS 256               // symbol taps
#define NGRID 16384
#define NHALF 8192
#define NIT   24                // CG iters (worst-case quad rel err ~9e-5)

__device__ float    g_logf[NHALF + 1];
__device__ double   g_szpart[NCTA];
__device__ double   g_qpart[NCTA];
__device__ double   g_c0;
__device__ unsigned g_cnt;
__device__ volatile unsigned g_gen;

__device__ __forceinline__ double warp_redd(double v) {
    #pragma unroll
    for (int o = 16; o; o >>= 1) v += __shfl_down_sync(0xffffffffu, v, o);
    return v;
}
__device__ __forceinline__ float warp_redf(float v) {
    #pragma unroll
    for (int o = 16; o; o >>= 1) v += __shfl_down_sync(0xffffffffu, v, o);
    return v;
}

// Grid-wide barrier (all NCTA CTAs resident).
__device__ __forceinline__ void gbar() {
    __syncthreads();
    if (threadIdx.x == 0) {
        __threadfence();
        unsigned gen = g_gen;
        if (atomicAdd(&g_cnt, 1u) == NCTA - 1u) {
            g_cnt = 0u;
            __threadfence();
            g_gen = gen + 1u;
        } else {
            while (g_gen == gen) { __nanosleep(64); }
        }
        __threadfence();
    }
    __syncthreads();
}

__global__ void __launch_bounds__(NTHR, 1)
gp_fused(const float* __restrict__ y,   const float* __restrict__ ssq,
         const float* __restrict__ ls,  const float* __restrict__ var,
         float* __restrict__ out)
{
    __shared__ float  s_tap[BTAPS + 1];
    __shared__ float  s_p[PADW];
    __shared__ double s_red[8];
    __shared__ double s_sz[8];
    __shared__ double s_ck2[2];

    const int t    = threadIdx.x;
    const int cta  = blockIdx.x;
    const int warp = t >> 5;
    const int lane = t & 31;

    // block-wide reduction, broadcast (fixed order)
    auto block_red = [&](double v) -> double {
        v = warp_redd(v);
        if (lane == 0) s_red[warp] = v;
        __syncthreads();
        double s = ((s_red[0] + s_red[1]) + (s_red[2] + s_red[3]))
                 + ((s_red[4] + s_red[5]) + (s_red[6] + s_red[7]));
        __syncthreads();
        return s;
    };

    // ---------------- taps (every CTA, redundant) ----------------------------
    {
        double L = (double)ls[0], V = (double)var[0], s2 = (double)ssq[0];
        double inv2 = 1.0 / (2.0 * L * L);
        for (int d = t; d <= BTAPS; d += NTHR) {
            double v = V * exp(-(double)d * (double)d * inv2);
            if (d == 0) v += s2;
            s_tap[d] = (float)v;
        }
    }
    for (int i = t; i < PADW; i += NTHR) s_p[i] = 0.f;
    __syncthreads();

    // ---------------- fully local windowed CG --------------------------------
    const int base = cta * CHUNK - HW;          // global index of window slot 0
    float x2[2], r2[2], p2[2], y2[2], mk[2];
    double acc0 = 0.0;
    #pragma unroll
    for (int q = 0; q < 2; q++) {
        int i = t + NTHR * q;                   // window slot
        int g = base + i;
        bool val = (i < WV) && (g >= 0) && (g < T_N);
        float yv = val ? y[g] : 0.f;
        mk[q] = val ? 1.f : 0.f;
        y2[q] = yv; x2[q] = 0.f; r2[q] = yv; p2[q] = yv;
        if (i < WV) s_p[BCV + i] = yv;
        acc0 += (double)yv * (double)yv;
    }
    double rho = block_red(acc0);               // also publishes s_p

    for (int it = 0; it < NIT; it++) {
        // matvec Ap on window (zero-Dirichlet pads/masks) + p.Ap
        float ap2[2];
        double pap = 0.0;
        #pragma unroll
        for (int q = 0; q < 2; q++) {
            int i = t + NTHR * q;
            int ic = (i < WV) ? i : (WV - 1);   // clamp dead slots (no OOB LDS)
            int c = BCV + ic;
            float a0 = s_tap[0] * s_p[c];
            float a1 = 0.f, a2 = 0.f, a3 = 0.f;
            #pragma unroll
            for (int d = 1; d <= 32; d++)
                a0 += s_tap[d] * (s_p[c - d] + s_p[c + d]);
            #pragma unroll
            for (int d = 33; d <= 64; d++)
                a1 += s_tap[d] * (s_p[c - d] + s_p[c + d]);
            #pragma unroll
            for (int d = 65; d <= 96; d++)
                a2 += s_tap[d] * (s_p[c - d] + s_p[c + d]);
            #pragma unroll
            for (int d = 97; d <= 128; d++)
                a3 += s_tap[d] * (s_p[c - d] + s_p[c + d]);
            float a = (a0 + a1) + (a2 + a3);
            ap2[q] = a;
            pap += (double)p2[q] * (double)a;   // p=0 at invalid slots
        }
        double paps = block_red(pap);
        float alpha = (float)(rho / paps);

        double rr = 0.0;
        #pragma unroll
        for (int q = 0; q < 2; q++) {
            x2[q] += alpha * p2[q];
            float rv = (r2[q] - alpha * ap2[q]) * mk[q];
            r2[q] = rv;
            rr += (double)rv * (double)rv;
        }
        double rhon = block_red(rr);
        float beta = (float)(rhon / rho);
        rho = rhon;

        #pragma unroll
        for (int q = 0; q < 2; q++) {
            int i = t + NTHR * q;
            float pv = r2[q] + beta * p2[q];
            p2[q] = pv;
            if (i < WV) s_p[BCV + i] = pv;
        }
        __syncthreads();
    }

    // quad partial over OWN interior chunk: slots [HW, HW+CHUNK) -> q=0 only
    {
        double qd = 0.0;
        if (t >= HW && t < HW + CHUNK)
            qd = (double)y2[0] * (double)x2[0];
        qd = block_red(qd);
        if (t == 0) g_qpart[cta] = qd;
    }

    // ---------------- symbol: logf[j], 64 j's per CTA ------------------------
    {
        int j = -1;
        if (t < 64) j = cta * 64 + t;
        else if (cta == NCTA - 1 && t == 64) j = NHALF;
        if (j >= 0) {
            const float sc = 1.0f / 8192.0f;
            float acc = 0.f;
            for (int d = 1; d < BTAPS; d++) {
                int m = (j * d) & (NGRID - 1);
                acc += s_tap[d] * cospif((float)m * sc);
            }
            g_logf[j] = logf(s_tap[0] + 2.f * acc);
        }
    }
    gbar();

    // ---------------- Szego partials: 2 harmonics per CTA (4 warps each) -----
    {
        int k = cta * 2 + (warp >> 2);          // 0..255
        int qt = warp & 3;
        const float sc = 1.0f / 8192.0f;
        float part = 0.f;
        for (int j = 1 + lane + 32 * qt; j < NHALF; j += 128) {
            int m = (j * k) & (NGRID - 1);
            part += g_logf[j] * cospif((float)m * sc);
        }
        part = warp_redf(part);
        if (lane == 0) s_sz[warp] = (double)part;
        __syncthreads();
        if (t == 0 || t == 128) {
            int h  = t >> 7;                     // 0 or 1
            int kk = cta * 2 + h;
            double s = (double)g_logf[0]
                     + ((kk & 1) ? -(double)g_logf[NHALF] : (double)g_logf[NHALF])
                     + 2.0 * (s_sz[4*h] + s_sz[4*h+1] + s_sz[4*h+2] + s_sz[4*h+3]);
            double ck = s / (double)NGRID;
            if (kk == 0) { g_c0 = ck; s_ck2[0] = 0.0; }
            else         s_ck2[h] = (double)kk * ck * ck;
        }
        __syncthreads();
        if (t == 0) g_szpart[cta] = s_ck2[0] + s_ck2[1];
    }
    gbar();

    // ---------------- combine (CTA 0) ----------------------------------------
    if (cta == 0) {
        double q  = (t < NCTA) ? __ldcg(&g_qpart[t])  : 0.0;  // bypass stale L1
        double sz = (t < NCTA) ? __ldcg(&g_szpart[t]) : 0.0;
        q  = warp_redd(q);
        sz = warp_redd(sz);
        if (lane == 0) { s_red[warp] = q; s_sz[warp] = sz; }
        __syncthreads();
        if (t == 0) {
            double Q  = ((s_red[0] + s_red[1]) + (s_red[2] + s_red[3]));
            double SZ = ((s_sz[0]  + s_sz[1])  + (s_sz[2]  + s_sz[3]));
            double logdet = (double)T_N * g_c0 + SZ;
            out[0] = (float)(-0.5 * Q - 0.5 * logdet);
        }
    }
}

extern "C" void kernel_launch(void* const* d_in, const int* in_sizes, int n_in,
                              void* d_out, int out_size) {
    const float* y   = (const float*)d_in[0];
    const float* ssq = (const float*)d_in[1];
    const float* ls  = (const float*)d_in[2];
    const float* var = (const float*)d_in[3];
    float* out = (float*)d_out;
    gp_fused<<<NCTA, NTHR>>>(y, ssq, ls, var, out);
}

// round 15
// speedup vs baseline: 3.1331x; 2.0941x over previous
#include <cuda_runtime.h>
#include <math.h>

// ---------------------------------------------------------------------------
// GP marginal log-likelihood, T=8192, RBF(l=32) + sigma^2 I.  ONE persistent
// kernel, 128 CTAs x 256 threads, all co-resident:
//   logdet : strong Szego  logdet = T*c0 + sum k*c_k^2  (c_k of log-symbol)
//   quad   : FULLY LOCAL windowed CG per CTA (A^{-1} decay e^{-0.031|i-j|}):
//            512-point principal-submatrix window (64-chunk + 224 halo),
//            zero cross-CTA sync in the iteration.  Band-128 matvec in smem.
// R14 vs R13: window 448->512 (all slots live, no clamp logic), NIT 24->20
// (worst-case bound 5.3e-4 still under tolerance), CG reductions fp64->fp32
// (kills DADD latency chains).  Band stays 128.
// ---------------------------------------------------------------------------

#define T_N   8192
#define NCTA  128
#define NTHR  256
#define CHUNK 64
#define HW    224               // window half-pad
#define WV    (CHUNK + 2*HW)    // 512 window slots (== 2*NTHR, all live)
#define BCV   128               // matvec half-band
#define PADW  (BCV + WV + BCV)  // 768 padded smem vector
#define BTAPS 256               // symbol taps
#define NGRID 16384
#define NHALF 8192
#define NIT   20                // CG iters (worst-case quad rel err 5.3e-4)

__device__ float    g_logf[NHALF + 1];
__device__ double   g_szpart[NCTA];
__device__ double   g_qpart[NCTA];
__device__ double   g_c0;
__device__ unsigned g_cnt;
__device__ volatile unsigned g_gen;

__device__ __forceinline__ double warp_redd(double v) {
    #pragma unroll
    for (int o = 16; o; o >>= 1) v += __shfl_down_sync(0xffffffffu, v, o);
    return v;
}
__device__ __forceinline__ float warp_redf(float v) {
    #pragma unroll
    for (int o = 16; o; o >>= 1) v += __shfl_down_sync(0xffffffffu, v, o);
    return v;
}

// Grid-wide barrier (all NCTA CTAs resident).
__device__ __forceinline__ void gbar() {
    __syncthreads();
    if (threadIdx.x == 0) {
        __threadfence();
        unsigned gen = g_gen;
        if (atomicAdd(&g_cnt, 1u) == NCTA - 1u) {
            g_cnt = 0u;
            __threadfence();
            g_gen = gen + 1u;
        } else {
            while (g_gen == gen) { __nanosleep(64); }
        }
        __threadfence();
    }
    __syncthreads();
}

__global__ void __launch_bounds__(NTHR, 1)
gp_fused(const float* __restrict__ y,   const float* __restrict__ ssq,
         const float* __restrict__ ls,  const float* __restrict__ var,
         float* __restrict__ out)
{
    __shared__ float  s_tap[BTAPS + 1];
    __shared__ float  s_p[PADW];
    __shared__ float  s_rf[8];
    __shared__ double s_red[8];
    __shared__ double s_sz[8];
    __shared__ double s_ck2[2];

    const int t    = threadIdx.x;
    const int cta  = blockIdx.x;
    const int warp = t >> 5;
    const int lane = t & 31;

    // block-wide f32 reduction, broadcast (fixed order)
    auto block_redf = [&](float v) -> float {
        v = warp_redf(v);
        if (lane == 0) s_rf[warp] = v;
        __syncthreads();
        float s = ((s_rf[0] + s_rf[1]) + (s_rf[2] + s_rf[3]))
                + ((s_rf[4] + s_rf[5]) + (s_rf[6] + s_rf[7]));
        __syncthreads();
        return s;
    };
    // block-wide f64 reduction (used outside hot loop)
    auto block_redd = [&](double v) -> double {
        v = warp_redd(v);
        if (lane == 0) s_red[warp] = v;
        __syncthreads();
        double s = ((s_red[0] + s_red[1]) + (s_red[2] + s_red[3]))
                 + ((s_red[4] + s_red[5]) + (s_red[6] + s_red[7]));
        __syncthreads();
        return s;
    };

    // ---------------- taps (every CTA, redundant) ----------------------------
    {
        double L = (double)ls[0], V = (double)var[0], s2 = (double)ssq[0];
        double inv2 = 1.0 / (2.0 * L * L);
        for (int d = t; d <= BTAPS; d += NTHR) {
            double v = V * exp(-(double)d * (double)d * inv2);
            if (d == 0) v += s2;
            s_tap[d] = (float)v;
        }
    }
    for (int i = t; i < PADW; i += NTHR) s_p[i] = 0.f;
    __syncthreads();

    // ---------------- fully local windowed CG --------------------------------
    const int base = cta * CHUNK - HW;          // global index of window slot 0
    float x2[2], r2[2], p2[2], y2[2], mk[2];
    #pragma unroll
    for (int q = 0; q < 2; q++) {
        int i = t + NTHR * q;                   // window slot (always < WV)
        int g = base + i;
        bool val = (g >= 0) && (g < T_N);
        float yv = val ? y[g] : 0.f;
        mk[q] = val ? 1.f : 0.f;
        y2[q] = yv; x2[q] = 0.f; r2[q] = yv; p2[q] = yv;
        s_p[BCV + i] = yv;
    }
    float rho = block_redf(r2[0]*r2[0] + r2[1]*r2[1]);  // also publishes s_p

    for (int it = 0; it < NIT; it++) {
        // matvec Ap on window (zero-Dirichlet pads) + p.Ap
        float ap2[2];
        float pap = 0.f;
        #pragma unroll
        for (int q = 0; q < 2; q++) {
            int c = BCV + t + NTHR * q;
            float a0 = s_tap[0] * s_p[c];
            float a1 = 0.f, a2 = 0.f, a3 = 0.f;
            #pragma unroll
            for (int d = 1; d <= 32; d++)
                a0 += s_tap[d] * (s_p[c - d] + s_p[c + d]);
            #pragma unroll
            for (int d = 33; d <= 64; d++)
                a1 += s_tap[d] * (s_p[c - d] + s_p[c + d]);
            #pragma unroll
            for (int d = 65; d <= 96; d++)
                a2 += s_tap[d] * (s_p[c - d] + s_p[c + d]);
            #pragma unroll
            for (int d = 97; d <= 128; d++)
                a3 += s_tap[d] * (s_p[c - d] + s_p[c + d]);
            float a = (a0 + a1) + (a2 + a3);
            ap2[q] = a;
            pap += p2[q] * a;                   // p=0 outside global range
        }
        float paps = block_redf(pap);
        float alpha = rho / paps;

        float rr = 0.f;
        #pragma unroll
        for (int q = 0; q < 2; q++) {
            x2[q] += alpha * p2[q];
            float rv = (r2[q] - alpha * ap2[q]) * mk[q];
            r2[q] = rv;
            rr += rv * rv;
        }
        float rhon = block_redf(rr);
        float beta = rhon / rho;
        rho = rhon;

        #pragma unroll
        for (int q = 0; q < 2; q++) {
            float pv = r2[q] + beta * p2[q];
            p2[q] = pv;
            s_p[BCV + t + NTHR * q] = pv;
        }
        __syncthreads();
    }

    // quad partial over OWN interior chunk: window slots [HW, HW+CHUNK)
    {
        double qd = 0.0;
        if (t >= HW && t < HW + CHUNK)          // q=0: slots 224..255
            qd += (double)y2[0] * (double)x2[0];
        if (t < HW + CHUNK - NTHR)              // q=1: slots 256..287 -> t<32
            qd += (double)y2[1] * (double)x2[1];
        qd = block_redd(qd);
        if (t == 0) g_qpart[cta] = qd;
    }

    // ---------------- symbol: logf[j], 64 j's per CTA ------------------------
    {
        int j = -1;
        if (t < 64) j = cta * 64 + t;
        else if (cta == NCTA - 1 && t == 64) j = NHALF;
        if (j >= 0) {
            const float sc = 1.0f / 8192.0f;
            float acc = 0.f;
            for (int d = 1; d < BTAPS; d++) {
                int m = (j * d) & (NGRID - 1);
                acc += s_tap[d] * cospif((float)m * sc);
            }
            g_logf[j] = logf(s_tap[0] + 2.f * acc);
        }
    }
    gbar();

    // ---------------- Szego partials: 2 harmonics per CTA (4 warps each) -----
    {
        int k = cta * 2 + (warp >> 2);          // 0..255
        int qt = warp & 3;
        const float sc = 1.0f / 8192.0f;
        float part = 0.f;
        for (int j = 1 + lane + 32 * qt; j < NHALF; j += 128) {
            int m = (j * k) & (NGRID - 1);
            part += g_logf[j] * cospif((float)m * sc);
        }
        part = warp_redf(part);
        if (lane == 0) s_sz[warp] = (double)part;
        __syncthreads();
        if (t == 0 || t == 128) {
            int h  = t >> 7;                     // 0 or 1
            int kk = cta * 2 + h;
            double s = (double)g_logf[0]
                     + ((kk & 1) ? -(double)g_logf[NHALF] : (double)g_logf[NHALF])
                     + 2.0 * (s_sz[4*h] + s_sz[4*h+1] + s_sz[4*h+2] + s_sz[4*h+3]);
            double ck = s / (double)NGRID;
            if (kk == 0) { g_c0 = ck; s_ck2[0] = 0.0; }
            else         s_ck2[h] = (double)kk * ck * ck;
        }
        __syncthreads();
        if (t == 0) g_szpart[cta] = s_ck2[0] + s_ck2[1];
    }
    gbar();

    // ---------------- combine (CTA 0) ----------------------------------------
    if (cta == 0) {
        double q  = (t < NCTA) ? __ldcg(&g_qpart[t])  : 0.0;  // bypass stale L1
        double sz = (t < NCTA) ? __ldcg(&g_szpart[t]) : 0.0;
        q  = warp_redd(q);
        sz = warp_redd(sz);
        if (lane == 0) { s_red[warp] = q; s_sz[warp] = sz; }
        __syncthreads();
        if (t == 0) {
            double Q  = ((s_red[0] + s_red[1]) + (s_red[2] + s_red[3]));
            double SZ = ((s_sz[0]  + s_sz[1])  + (s_sz[2]  + s_sz[3]));
            double logdet = (double)T_N * g_c0 + SZ;
            out[0] = (float)(-0.5 * Q - 0.5 * logdet);
        }
    }
}

extern "C" void kernel_launch(void* const* d_in, const int* in_sizes, int n_in,
                              void* d_out, int out_size) {
    const float* y   = (const float*)d_in[0];
    const float* ssq = (const float*)d_in[1];
    const float* ls  = (const float*)d_in[2];
    const float* var = (const float*)d_in[3];
    float* out = (float*)d_out;
    gp_fused<<<NCTA, NTHR>>>(y, ssq, ls, var, out);
}

// round 16
// speedup vs baseline: 4.5913x; 1.4654x over previous
#include <cuda_runtime.h>
#include <math.h>

// ---------------------------------------------------------------------------
// GP marginal log-likelihood, T=8192, RBF(l=32) + sigma^2 I.  ONE persistent
// kernel, 128 CTAs x 256 threads, all co-resident:
//   logdet : strong Szego  logdet = T*c0 + sum k*c_k^2  (c_k of log-symbol)
//   quad   : FULLY LOCAL windowed CG per CTA, 512-slot window (64 + 2*224),
//            band-128 matvec in smem, zero cross-CTA sync in the iteration.
// R16 vs R15: thread owns CONSECUTIVE slot pair (2t,2t+1); matvec uses
// float2 sliding loads (one 8B load feeds 4 tap*output terms) -> 2x crossbar
// bytes, ~2.5x fewer LDS instrs.  NIT 20->16 (measured flat error 24->20
// shows CG component is below the 7e-6 floor).  Effective operator remains
// symmetric (tap[129] spill terms pair across even/odd outputs).
// ---------------------------------------------------------------------------

#define T_N   8192
#define NCTA  128
#define NTHR  256
#define CHUNK 64
#define HW    224               // window half-pad
#define WV    (CHUNK + 2*HW)    // 512 window slots
#define BCV   128               // matvec half-band
#define PADW  (BCV + WV + BCV)  // 768 padded smem vector
#define BTAPS 256               // symbol taps
#define NGRID 16384
#define NHALF 8192
#define NIT   16                // CG iters (measured-evidence margin ~16x)

__device__ float    g_logf[NHALF + 1];
__device__ double   g_szpart[NCTA];
__device__ double   g_qpart[NCTA];
__device__ double   g_c0;
__device__ unsigned g_cnt;
__device__ volatile unsigned g_gen;

__device__ __forceinline__ double warp_redd(double v) {
    #pragma unroll
    for (int o = 16; o; o >>= 1) v += __shfl_down_sync(0xffffffffu, v, o);
    return v;
}
__device__ __forceinline__ float warp_redf(float v) {
    #pragma unroll
    for (int o = 16; o; o >>= 1) v += __shfl_down_sync(0xffffffffu, v, o);
    return v;
}

// Grid-wide barrier (all NCTA CTAs resident).
__device__ __forceinline__ void gbar() {
    __syncthreads();
    if (threadIdx.x == 0) {
        __threadfence();
        unsigned gen = g_gen;
        if (atomicAdd(&g_cnt, 1u) == NCTA - 1u) {
            g_cnt = 0u;
            __threadfence();
            g_gen = gen + 1u;
        } else {
            while (g_gen == gen) { __nanosleep(64); }
        }
        __threadfence();
    }
    __syncthreads();
}

__global__ void __launch_bounds__(NTHR, 1)
gp_fused(const float* __restrict__ y,   const float* __restrict__ ssq,
         const float* __restrict__ ls,  const float* __restrict__ var,
         float* __restrict__ out)
{
    __shared__ __align__(16) float  s_tap[BTAPS + 2];
    __shared__ __align__(16) float  s_p[PADW];
    __shared__ float  s_rf[8];
    __shared__ double s_red[8];
    __shared__ double s_sz[8];
    __shared__ double s_ck2[2];

    const int t    = threadIdx.x;
    const int cta  = blockIdx.x;
    const int warp = t >> 5;
    const int lane = t & 31;

    auto block_redf = [&](float v) -> float {
        v = warp_redf(v);
        if (lane == 0) s_rf[warp] = v;
        __syncthreads();
        float s = ((s_rf[0] + s_rf[1]) + (s_rf[2] + s_rf[3]))
                + ((s_rf[4] + s_rf[5]) + (s_rf[6] + s_rf[7]));
        __syncthreads();
        return s;
    };
    auto block_redd = [&](double v) -> double {
        v = warp_redd(v);
        if (lane == 0) s_red[warp] = v;
        __syncthreads();
        double s = ((s_red[0] + s_red[1]) + (s_red[2] + s_red[3]))
                 + ((s_red[4] + s_red[5]) + (s_red[6] + s_red[7]));
        __syncthreads();
        return s;
    };

    // ---------------- taps (every CTA, redundant) ----------------------------
    {
        double L = (double)ls[0], V = (double)var[0], s2 = (double)ssq[0];
        double inv2 = 1.0 / (2.0 * L * L);
        for (int d = t; d <= BTAPS + 1; d += NTHR) {
            double v = V * exp(-(double)d * (double)d * inv2);
            if (d == 0) v += s2;
            s_tap[d] = (float)v;
        }
    }
    for (int i = t; i < PADW; i += NTHR) s_p[i] = 0.f;
    __syncthreads();

    // ---------------- fully local windowed CG (pair per thread) --------------
    const int base = cta * CHUNK - HW;          // global index of window slot 0
    const int c0   = BCV + 2 * t;               // smem index of first slot
    float x0 = 0.f, x1 = 0.f, r0, r1, p0, p1, y0, y1, mk0, mk1;
    {
        int g0 = base + 2 * t, g1 = g0 + 1;
        mk0 = (g0 >= 0 && g0 < T_N) ? 1.f : 0.f;
        mk1 = (g1 >= 0 && g1 < T_N) ? 1.f : 0.f;
        y0 = mk0 ? y[g0] : 0.f;
        y1 = mk1 ? y[g1] : 0.f;
        r0 = y0; r1 = y1; p0 = y0; p1 = y1;
        *reinterpret_cast<float2*>(&s_p[c0]) = make_float2(p0, p1);
    }
    float rho = block_redf(r0 * r0 + r1 * r1);  // also publishes s_p

    const float tap0 = s_tap[0];
    const float tap1 = s_tap[1];

    for (int it = 0; it < NIT; it++) {
        // matvec: ap for slots c0, c0+1 via float2 sliding loads
        float a0a = tap0 * p0, a0b = tap1 * p1;
        float a1a = tap0 * p1, a1b = tap1 * p0;
        float tcar = tap1;                      // tap[d-1] carry
        #pragma unroll 16
        for (int d = 2; d <= BCV; d += 2) {
            float2 td = *reinterpret_cast<const float2*>(&s_tap[d]); // tap[d], tap[d+1]
            float2 l  = *reinterpret_cast<const float2*>(&s_p[c0 - d]); // P[c0-d], P[c0-d+1]
            float2 rr = *reinterpret_cast<const float2*>(&s_p[c0 + d]); // P[c0+d], P[c0+d+1]
            a0a += td.x * (l.x + rr.x);
            a0b += tcar * l.y;
            a0b += td.y * rr.y;
            a1a += td.x * (l.y + rr.y);
            a1b += td.y * l.x;
            a1b += tcar * rr.x;
            tcar = td.y;
        }
        float ap0 = a0a + a0b;
        float ap1 = a1a + a1b;

        float paps = block_redf(p0 * ap0 + p1 * ap1);
        float alpha = rho / paps;

        x0 += alpha * p0;  x1 += alpha * p1;
        r0 = (r0 - alpha * ap0) * mk0;
        r1 = (r1 - alpha * ap1) * mk1;
        float rhon = block_redf(r0 * r0 + r1 * r1);
        float beta = rhon / rho;
        rho = rhon;

        p0 = r0 + beta * p0;
        p1 = r1 + beta * p1;
        *reinterpret_cast<float2*>(&s_p[c0]) = make_float2(p0, p1);
        __syncthreads();
    }

    // quad partial over OWN interior chunk: slots [224,288) -> t in [112,144)
    {
        double qd = 0.0;
        if (t >= HW / 2 && t < (HW + CHUNK) / 2)
            qd = (double)y0 * (double)x0 + (double)y1 * (double)x1;
        qd = block_redd(qd);
        if (t == 0) g_qpart[cta] = qd;
    }

    // ---------------- symbol: logf[j], 64 j's per CTA ------------------------
    {
        int j = -1;
        if (t < 64) j = cta * 64 + t;
        else if (cta == NCTA - 1 && t == 64) j = NHALF;
        if (j >= 0) {
            const float sc = 1.0f / 8192.0f;
            float acc = 0.f;
            for (int d = 1; d < BTAPS; d++) {
                int m = (j * d) & (NGRID - 1);
                acc += s_tap[d] * cospif((float)m * sc);
            }
            g_logf[j] = logf(s_tap[0] + 2.f * acc);
        }
    }
    gbar();

    // ---------------- Szego partials: 2 harmonics per CTA (4 warps each) -----
    {
        int k = cta * 2 + (warp >> 2);          // 0..255
        int qt = warp & 3;
        const float sc = 1.0f / 8192.0f;
        float part = 0.f;
        for (int j = 1 + lane + 32 * qt; j < NHALF; j += 128) {
            int m = (j * k) & (NGRID - 1);
            part += g_logf[j] * cospif((float)m * sc);
        }
        part = warp_redf(part);
        if (lane == 0) s_sz[warp] = (double)part;
        __syncthreads();
        if (t == 0 || t == 128) {
            int h  = t >> 7;                     // 0 or 1
            int kk = cta * 2 + h;
            double s = (double)g_logf[0]
                     + ((kk & 1) ? -(double)g_logf[NHALF] : (double)g_logf[NHALF])
                     + 2.0 * (s_sz[4*h] + s_sz[4*h+1] + s_sz[4*h+2] + s_sz[4*h+3]);
            double ck = s / (double)NGRID;
            if (kk == 0) { g_c0 = ck; s_ck2[0] = 0.0; }
            else         s_ck2[h] = (double)kk * ck * ck;
        }
        __syncthreads();
        if (t == 0) g_szpart[cta] = s_ck2[0] + s_ck2[1];
    }
    gbar();

    // ---------------- combine (CTA 0) ----------------------------------------
    if (cta == 0) {
        double q  = (t < NCTA) ? __ldcg(&g_qpart[t])  : 0.0;  // bypass stale L1
        double sz = (t < NCTA) ? __ldcg(&g_szpart[t]) : 0.0;
        q  = warp_redd(q);
        sz = warp_redd(sz);
        if (lane == 0) { s_red[warp] = q; s_sz[warp] = sz; }
        __syncthreads();
        if (t == 0) {
            double Q  = ((s_red[0] + s_red[1]) + (s_red[2] + s_red[3]));
            double SZ = ((s_sz[0]  + s_sz[1])  + (s_sz[2]  + s_sz[3]));
            double logdet = (double)T_N * g_c0 + SZ;
            out[0] = (float)(-0.5 * Q - 0.5 * logdet);
        }
    }
}

extern "C" void kernel_launch(void* const* d_in, const int* in_sizes, int n_in,
                              void* d_out, int out_size) {
    const float* y   = (const float*)d_in[0];
    const float* ssq = (const float*)d_in[1];
    const float* ls  = (const float*)d_in[2];
    const float* var = (const float*)d_in[3];
    float* out = (float*)d_out;
    gp_fused<<<NCTA, NTHR>>>(y, ssq, ls, var, out);
}

// round 17
// speedup vs baseline: 5.3774x; 1.1712x over previous
#include <cuda_runtime.h>
#include <math.h>

// ---------------------------------------------------------------------------
// GP marginal log-likelihood, T=8192, RBF(l=32) + sigma^2 I.  ONE persistent
// kernel, 128 CTAs x 256 threads, all co-resident:
//   logdet : strong Szego  logdet = T*c0 + sum k*c_k^2  (c_k of log-symbol)
//   quad   : FULLY LOCAL windowed CG per CTA, 512-slot window (64 + 2*224),
//            band-128 float2 matvec in smem, zero cross-CTA iteration sync.
// R17 vs R16: Chronopoulos-Gear pipelined CG -> ONE joint (r.r, w.r)
// reduction + ONE matvec per iteration, 2 barriers/iter (was 2 reductions,
// 3 bars); NIT 16->12 (measured error rate 0.64/iter => ~8e-5, 12x margin);
// final iteration skips its dead matvec+reduction.
// ---------------------------------------------------------------------------

#define T_N   8192
#define NCTA  128
#define NTHR  256
#define CHUNK 64
#define HW    224               // window half-pad
#define WV    (CHUNK + 2*HW)    // 512 window slots
#define BCV   128               // matvec half-band
#define PADW  (BCV + WV + BCV)  // 768 padded smem vector
#define BTAPS 256               // symbol taps
#define NGRID 16384
#define NHALF 8192
#define NIT   12                // CG steps (measured-evidence ~8e-5)

__device__ float    g_logf[NHALF + 1];
__device__ double   g_szpart[NCTA];
__device__ double   g_qpart[NCTA];
__device__ double   g_c0;
__device__ unsigned g_cnt;
__device__ volatile unsigned g_gen;

__device__ __forceinline__ double warp_redd(double v) {
    #pragma unroll
    for (int o = 16; o; o >>= 1) v += __shfl_down_sync(0xffffffffu, v, o);
    return v;
}
__device__ __forceinline__ float warp_redf(float v) {
    #pragma unroll
    for (int o = 16; o; o >>= 1) v += __shfl_down_sync(0xffffffffu, v, o);
    return v;
}

// Grid-wide barrier (all NCTA CTAs resident).
__device__ __forceinline__ void gbar() {
    __syncthreads();
    if (threadIdx.x == 0) {
        __threadfence();
        unsigned gen = g_gen;
        if (atomicAdd(&g_cnt, 1u) == NCTA - 1u) {
            g_cnt = 0u;
            __threadfence();
            g_gen = gen + 1u;
        } else {
            while (g_gen == gen) { __nanosleep(64); }
        }
        __threadfence();
    }
    __syncthreads();
}

__global__ void __launch_bounds__(NTHR, 1)
gp_fused(const float* __restrict__ y,   const float* __restrict__ ssq,
         const float* __restrict__ ls,  const float* __restrict__ var,
         float* __restrict__ out)
{
    __shared__ __align__(16) float  s_tap[BTAPS + 2];
    __shared__ __align__(16) float  s_p[PADW];
    __shared__ float2 s_rf2[8];
    __shared__ double s_red[8];
    __shared__ double s_sz[8];
    __shared__ double s_ck2[2];

    const int t    = threadIdx.x;
    const int cta  = blockIdx.x;
    const int warp = t >> 5;
    const int lane = t & 31;

    auto block_redd = [&](double v) -> double {
        v = warp_redd(v);
        if (lane == 0) s_red[warp] = v;
        __syncthreads();
        double s = ((s_red[0] + s_red[1]) + (s_red[2] + s_red[3]))
                 + ((s_red[4] + s_red[5]) + (s_red[6] + s_red[7]));
        __syncthreads();
        return s;
    };

    // ---------------- taps (every CTA, redundant) ----------------------------
    {
        double L = (double)ls[0], V = (double)var[0], s2 = (double)ssq[0];
        double inv2 = 1.0 / (2.0 * L * L);
        for (int d = t; d <= BTAPS + 1; d += NTHR) {
            double v = V * exp(-(double)d * (double)d * inv2);
            if (d == 0) v += s2;
            s_tap[d] = (float)v;
        }
    }
    for (int i = t; i < PADW; i += NTHR) s_p[i] = 0.f;
    __syncthreads();

    // ---------------- fully local windowed pipelined CG ----------------------
    const int base = cta * CHUNK - HW;
    const int c0   = BCV + 2 * t;
    float x0 = 0.f, x1 = 0.f, p0 = 0.f, p1 = 0.f, s0 = 0.f, s1 = 0.f;
    float r0, r1, y0, y1, mk0, mk1;
    {
        int g0 = base + 2 * t, g1 = g0 + 1;
        mk0 = (g0 >= 0 && g0 < T_N) ? 1.f : 0.f;
        mk1 = (g1 >= 0 && g1 < T_N) ? 1.f : 0.f;
        y0 = mk0 ? y[g0] : 0.f;
        y1 = mk1 ? y[g1] : 0.f;
        r0 = y0; r1 = y1;
        *reinterpret_cast<float2*>(&s_p[c0]) = make_float2(r0, r1);
    }
    __syncthreads();

    const float tap0 = s_tap[0];
    const float tap1 = s_tap[1];

    // matvec on s_p window -> (w0, w1) for slots c0, c0+1
    auto matvec = [&](float v0, float v1, float& w0, float& w1) {
        float a0a = tap0 * v0, a0b = tap1 * v1;
        float a1a = tap0 * v1, a1b = tap1 * v0;
        float tcar = tap1;
        #pragma unroll 16
        for (int d = 2; d <= BCV; d += 2) {
            float2 td = *reinterpret_cast<const float2*>(&s_tap[d]);
            float2 l  = *reinterpret_cast<const float2*>(&s_p[c0 - d]);
            float2 rr = *reinterpret_cast<const float2*>(&s_p[c0 + d]);
            a0a += td.x * (l.x + rr.x);
            a0b += tcar * l.y;
            a0b += td.y * rr.y;
            a1a += td.x * (l.y + rr.y);
            a1b += td.y * l.x;
            a1b += tcar * rr.x;
            tcar = td.y;
        }
        w0 = a0a + a0b;
        w1 = a1a + a1b;
    };

    float w0, w1;
    matvec(r0, r1, w0, w1);

    // joint reduction of (r.r, w.r); bar1 only — caller publishes + bar2
    float rho, mu, alpha, beta = 0.f;
    {
        float a = r0 * r0 + r1 * r1;
        float b = w0 * r0 + w1 * r1;
        #pragma unroll
        for (int o = 16; o; o >>= 1) {
            a += __shfl_down_sync(0xffffffffu, a, o);
            b += __shfl_down_sync(0xffffffffu, b, o);
        }
        if (lane == 0) s_rf2[warp] = make_float2(a, b);
        __syncthreads();
        float sa = ((s_rf2[0].x + s_rf2[1].x) + (s_rf2[2].x + s_rf2[3].x))
                 + ((s_rf2[4].x + s_rf2[5].x) + (s_rf2[6].x + s_rf2[7].x));
        float sb = ((s_rf2[0].y + s_rf2[1].y) + (s_rf2[2].y + s_rf2[3].y))
                 + ((s_rf2[4].y + s_rf2[5].y) + (s_rf2[6].y + s_rf2[7].y));
        rho = sa; mu = sb; alpha = sa / sb;
    }

    for (int it = 0; it < NIT; it++) {
        // vector updates (registers only)
        p0 = r0 + beta * p0;  p1 = r1 + beta * p1;
        s0 = w0 + beta * s0;  s1 = w1 + beta * s1;
        x0 += alpha * p0;     x1 += alpha * p1;
        r0 = (r0 - alpha * s0) * mk0;
        r1 = (r1 - alpha * s1) * mk1;

        if (it < NIT - 1) {
            // publish r (doubles as s_rf2 reuse guard: all reads done pre-bar)
            *reinterpret_cast<float2*>(&s_p[c0]) = make_float2(r0, r1);
            __syncthreads();

            matvec(r0, r1, w0, w1);

            float a = r0 * r0 + r1 * r1;
            float b = w0 * r0 + w1 * r1;
            #pragma unroll
            for (int o = 16; o; o >>= 1) {
                a += __shfl_down_sync(0xffffffffu, a, o);
                b += __shfl_down_sync(0xffffffffu, b, o);
            }
            if (lane == 0) s_rf2[warp] = make_float2(a, b);
            __syncthreads();
            float sa = ((s_rf2[0].x + s_rf2[1].x) + (s_rf2[2].x + s_rf2[3].x))
                     + ((s_rf2[4].x + s_rf2[5].x) + (s_rf2[6].x + s_rf2[7].x));
            float sb = ((s_rf2[0].y + s_rf2[1].y) + (s_rf2[2].y + s_rf2[3].y))
                     + ((s_rf2[4].y + s_rf2[5].y) + (s_rf2[6].y + s_rf2[7].y));
            beta  = sa / rho;
            alpha = sa / (sb - sa * (beta / alpha));
            rho   = sa;
        }
    }
    __syncthreads();

    // quad partial over OWN interior chunk: slots [224,288) -> t in [112,144)
    {
        double qd = 0.0;
        if (t >= HW / 2 && t < (HW + CHUNK) / 2)
            qd = (double)y0 * (double)x0 + (double)y1 * (double)x1;
        qd = block_redd(qd);
        if (t == 0) g_qpart[cta] = qd;
    }

    // ---------------- symbol: logf[j], 64 j's per CTA ------------------------
    {
        int j = -1;
        if (t < 64) j = cta * 64 + t;
        else if (cta == NCTA - 1 && t == 64) j = NHALF;
        if (j >= 0) {
            const float sc = 1.0f / 8192.0f;
            float acc = 0.f;
            for (int d = 1; d < BTAPS; d++) {
                int m = (j * d) & (NGRID - 1);
                acc += s_tap[d] * cospif((float)m * sc);
            }
            g_logf[j] = logf(s_tap[0] + 2.f * acc);
        }
    }
    gbar();

    // ---------------- Szego partials: 2 harmonics per CTA (4 warps each) -----
    {
        int k = cta * 2 + (warp >> 2);          // 0..255
        int qt = warp & 3;
        const float sc = 1.0f / 8192.0f;
        float part = 0.f;
        for (int j = 1 + lane + 32 * qt; j < NHALF; j += 128) {
            int m = (j * k) & (NGRID - 1);
            part += g_logf[j] * cospif((float)m * sc);
        }
        part = warp_redf(part);
        if (lane == 0) s_sz[warp] = (double)part;
        __syncthreads();
        if (t == 0 || t == 128) {
            int h  = t >> 7;                     // 0 or 1
            int kk = cta * 2 + h;
            double s = (double)g_logf[0]
                     + ((kk & 1) ? -(double)g_logf[NHALF] : (double)g_logf[NHALF])
                     + 2.0 * (s_sz[4*h] + s_sz[4*h+1] + s_sz[4*h+2] + s_sz[4*h+3]);
            double ck = s / (double)NGRID;
            if (kk == 0) { g_c0 = ck; s_ck2[0] = 0.0; }
            else         s_ck2[h] = (double)kk * ck * ck;
        }
        __syncthreads();
        if (t == 0) g_szpart[cta] = s_ck2[0] + s_ck2[1];
    }
    gbar();

    // ---------------- combine (CTA 0) ----------------------------------------
    if (cta == 0) {
        double q  = (t < NCTA) ? __ldcg(&g_qpart[t])  : 0.0;  // bypass stale L1
        double sz = (t < NCTA) ? __ldcg(&g_szpart[t]) : 0.0;
        q  = warp_redd(q);
        sz = warp_redd(sz);
        if (lane == 0) { s_red[warp] = q; s_sz[warp] = sz; }
        __syncthreads();
        if (t == 0) {
            double Q  = ((s_red[0] + s_red[1]) + (s_red[2] + s_red[3]));
            double SZ = ((s_sz[0]  + s_sz[1])  + (s_sz[2]  + s_sz[3]));
            double logdet = (double)T_N * g_c0 + SZ;
            out[0] = (float)(-0.5 * Q - 0.5 * logdet);
        }
    }
}

extern "C" void kernel_launch(void* const* d_in, const int* in_sizes, int n_in,
                              void* d_out, int out_size) {
    const float* y   = (const float*)d_in[0];
    const float* ssq = (const float*)d_in[1];
    const float* ls  = (const float*)d_in[2];
    const float* var = (const float*)d_in[3];
    float* out = (float*)d_out;
    gp_fused<<<NCTA, NTHR>>>(y, ssq, ls, var, out);
}